// round 12
// baseline (speedup 1.0000x reference)
#include <cuda_runtime.h>
#include <cuda_bf16.h>
#include <math.h>
#include <stdint.h>

// ---------------- problem constants ----------------
#define IMGD   64
#define BATCH  512
#define UNITS  256
#define STEPS  10
#define GATE   (4*UNITS)          // 1024
#define PIX    (IMGD*IMGD)        // 4096
#define K_ENC  (PIX + 2*UNITS)    // 4608
#define K_DEC  (2*UNITS)          // 512
#define K_CAN  UNITS              // 256
#define KP_ENC (3*K_ENC)          // 13824
#define KP_DEC (3*K_DEC)          // 1536
#define KP_CAN (3*K_CAN)          // 768

#define ENC_SPLITS 9              // grid (8,8,9) = 576 CTAs @ 4/SM = ~1 wave
#define DEC_SPLITS 8              // grid (8,8,8) = 512 CTAs

// ---------------- scratch (device globals) ----------------
__device__ __align__(16) __nv_bfloat16 g_Be[(size_t)KP_ENC * GATE];
__device__ __align__(16) __nv_bfloat16 g_Bd[(size_t)KP_DEC * GATE];
__device__ __align__(16) __nv_bfloat16 g_Bc[(size_t)KP_CAN * PIX];
__device__ __align__(16) __nv_bfloat16 g_Aeb[(size_t)BATCH * KP_ENC];
__device__ __align__(16) __nv_bfloat16 g_Adb[(size_t)BATCH * KP_DEC];
__device__ __align__(16) __nv_bfloat16 g_Acb[(size_t)BATCH * KP_CAN];
__device__ __align__(16) float g_part[(size_t)ENC_SPLITS * BATCH * GATE];
__device__ __align__(16) float g_ce[BATCH * UNITS];
__device__ __align__(16) float g_cd[BATCH * UNITS];

__device__ __forceinline__ float sigmoidf(float x) { return 1.f / (1.f + expf(-x)); }
__device__ __forceinline__ void split_bf16(float v, __nv_bfloat16& hi, __nv_bfloat16& lo) {
    hi = __float2bfloat16(v);
    lo = __float2bfloat16(v - __bfloat162float(hi));
}

// ---------------- PTX helpers ----------------
__device__ __forceinline__ uint32_t smem_u32(const void* p) {
    uint32_t a;
    asm("{ .reg .u64 t; cvta.to.shared.u64 t, %1; cvt.u32.u64 %0, t; }" : "=r"(a) : "l"(p));
    return a;
}
#define CP_ASYNC16(dst, src) \
    asm volatile("cp.async.cg.shared.global [%0], [%1], 16;\n" :: "r"(dst), "l"(src))
#define CP_COMMIT() asm volatile("cp.async.commit_group;\n")

__device__ __forceinline__ void ldmatrix_x4(uint32_t* r, const void* p) {
    uint32_t a = smem_u32(p);
    asm volatile("ldmatrix.sync.aligned.m8n8.x4.shared.b16 {%0,%1,%2,%3}, [%4];\n"
                 : "=r"(r[0]), "=r"(r[1]), "=r"(r[2]), "=r"(r[3]) : "r"(a));
}
__device__ __forceinline__ void ldmatrix_x4_trans(uint32_t* r, const void* p) {
    uint32_t a = smem_u32(p);
    asm volatile("ldmatrix.sync.aligned.m8n8.x4.trans.shared.b16 {%0,%1,%2,%3}, [%4];\n"
                 : "=r"(r[0]), "=r"(r[1]), "=r"(r[2]), "=r"(r[3]) : "r"(a));
}
__device__ __forceinline__ void mma_bf16(float* d, const uint32_t* a, uint32_t b0, uint32_t b1) {
    asm volatile("mma.sync.aligned.m16n8k16.row.col.f32.bf16.bf16.f32 "
                 "{%0,%1,%2,%3}, {%4,%5,%6,%7}, {%8,%9}, {%0,%1,%2,%3};\n"
                 : "+f"(d[0]), "+f"(d[1]), "+f"(d[2]), "+f"(d[3])
                 : "r"(a[0]), "r"(a[1]), "r"(a[2]), "r"(a[3]), "r"(b0), "r"(b1));
}

// ---------------- HMMA GEMM: 64x128 tile, 128 thr (4 warps), BK=32, 4 stages, 4 CTA/SM ----
// Warp tile 32x64 (identical per-warp mix to the validated config); 4 small CTAs
// decouple barriers: each SMSP holds 4 warps from 4 different CTAs.
#define A_ROW_B 80                 // 32*2 + 16 pad
#define B_ROW_B 272                // 128*2 + 16 pad
#define CTA_M   64
#define STG_BYTES (CTA_M * A_ROW_B + 32 * B_ROW_B)   // 5120 + 8704 = 13824
#define GEMM_SMEM (4 * STG_BYTES)                    // 55296

template<int MODE>
__global__ void __launch_bounds__(128, 4) gemm_hmma(
    const __nv_bfloat16* __restrict__ A, int lda,
    const __nv_bfloat16* __restrict__ B, int ldb,
    float* __restrict__ out, int ldc, int kPerSplit,
    const float* __restrict__ bias,
    const float* __restrict__ x, __nv_bfloat16* __restrict__ aeb)
{
    extern __shared__ __align__(16) char sm[];
    const int tid  = threadIdx.x;
    const int m0   = blockIdx.y * CTA_M;
    const int n0   = blockIdx.x * 128;
    const int z    = blockIdx.z;
    const int kbase = z * kPerSplit;
    const int S    = kPerSplit / 32;
    const int warp = tid >> 5, lane = tid & 31;
    const int wm   = (warp >> 1) * 32;   // 2 warp-rows
    const int wn   = (warp & 1) * 64;    // 2 warp-cols

    auto prefetch = [&](int s) {
        char* st = sm + (s & 3) * STG_BYTES;
        const int k0 = kbase + s * 32;
        #pragma unroll
        for (int i = 0; i < 2; i++) {          // A: 64 x 32 (256 chunks / 128 thr)
            int c = tid + 128 * i;
            int row = c >> 2, col = (c & 3) * 8;
            CP_ASYNC16(smem_u32(st + row * A_ROW_B + col * 2),
                       A + (size_t)(m0 + row) * lda + k0 + col);
        }
        #pragma unroll
        for (int i = 0; i < 4; i++) {          // B: 32 x 128 (512 chunks / 128 thr)
            int c = tid + 128 * i;
            int row = c >> 4, col = (c & 15) * 8;
            CP_ASYNC16(smem_u32(st + CTA_M * A_ROW_B + row * B_ROW_B + col * 2),
                       B + (size_t)(k0 + row) * ldb + n0 + col);
        }
        CP_COMMIT();
    };

    float acc[2][8][4] = {};
    prefetch(0); prefetch(1); prefetch(2);

    for (int s = 0; s < S; s++) {
        int rem = S - 1 - s;
        if (rem >= 2)      asm volatile("cp.async.wait_group 2;\n" ::: "memory");
        else if (rem == 1) asm volatile("cp.async.wait_group 1;\n" ::: "memory");
        else               asm volatile("cp.async.wait_group 0;\n" ::: "memory");
        __syncthreads();
        if (s + 3 < S) prefetch(s + 3);

        const char* st = sm + (s & 3) * STG_BYTES;
        const char* sb = st + CTA_M * A_ROW_B;
        #pragma unroll
        for (int kk = 0; kk < 32; kk += 16) {
            uint32_t af[2][4], bfr[4][4];
            #pragma unroll
            for (int mt = 0; mt < 2; mt++)
                ldmatrix_x4(af[mt], st + (wm + mt * 16 + (lane & 15)) * A_ROW_B
                                       + (kk + (lane >> 4) * 8) * 2);
            #pragma unroll
            for (int g = 0; g < 4; g++)
                ldmatrix_x4_trans(bfr[g], sb + (kk + (lane & 15)) * B_ROW_B
                                             + (wn + g * 16 + (lane >> 4) * 8) * 2);
            #pragma unroll
            for (int mt = 0; mt < 2; mt++)
                #pragma unroll
                for (int nt = 0; nt < 8; nt++)
                    mma_bf16(acc[mt][nt], af[mt],
                             bfr[nt >> 1][(nt & 1) * 2], bfr[nt >> 1][(nt & 1) * 2 + 1]);
        }
    }

    if (MODE == 0) {
        float* o = out + (size_t)z * (BATCH * ldc);
        #pragma unroll
        for (int mt = 0; mt < 2; mt++) {
            #pragma unroll
            for (int nt = 0; nt < 8; nt++) {
                int r = m0 + wm + mt * 16 + (lane >> 2);
                int c = n0 + wn + nt * 8 + (lane & 3) * 2;
                *reinterpret_cast<float2*>(&o[(size_t)r * ldc + c]) =
                    make_float2(acc[mt][nt][0], acc[mt][nt][1]);
                *reinterpret_cast<float2*>(&o[(size_t)(r + 8) * ldc + c]) =
                    make_float2(acc[mt][nt][2], acc[mt][nt][3]);
            }
        }
    } else {
        #pragma unroll
        for (int mt = 0; mt < 2; mt++) {
            #pragma unroll
            for (int nt = 0; nt < 8; nt++) {
                int c = n0 + wn + nt * 8 + (lane & 3) * 2;
                float b0 = bias[c], b1 = bias[c + 1];
                #pragma unroll
                for (int pr = 0; pr < 2; pr++) {
                    int r = m0 + wm + mt * 16 + (lane >> 2) + 8 * pr;
                    size_t o = (size_t)r * ldc + c;
                    float2 old = *reinterpret_cast<const float2*>(&out[o]);
                    float v0 = acc[mt][nt][2 * pr]     + old.x + b0;
                    float v1 = acc[mt][nt][2 * pr + 1] + old.y + b1;
                    *reinterpret_cast<float2*>(&out[o]) = make_float2(v0, v1);
                    float xv0 = x[o] - sigmoidf(v0);
                    float xv1 = x[o + 1] - sigmoidf(v1);
                    __nv_bfloat16 h0, l0, h1, l1;
                    split_bf16(xv0, h0, l0);
                    split_bf16(xv1, h1, l1);
                    size_t ab = (size_t)r * KP_ENC + c;
                    aeb[ab]             = h0; aeb[ab + 1]             = h1;
                    aeb[ab + K_ENC]     = h0; aeb[ab + K_ENC + 1]     = h1;
                    aeb[ab + 2 * K_ENC] = l0; aeb[ab + 2 * K_ENC + 1] = l1;
                }
            }
        }
    }
}

// ---------------- setup kernels (exactly 3 launches; harness adds 2 before) ----
__global__ void build_w1_kernel(const float* __restrict__ ek, const float* __restrict__ er) {
    int idx = blockIdx.x * blockDim.x + threadIdx.x;
    if (idx >= K_ENC * GATE) return;
    int row = idx / GATE;
    int n   = idx - row * GATE;
    float v;
    if (row < PIX) {
        int r = row >> 6, c = row & 63;
        v = 0.f;
        #pragma unroll
        for (int dr = 0; dr < 3; dr++) {
            int rr = r - dr;
            if (rr >= 0 && (rr & 1) == 0) {
                int pr = rr >> 1;
                #pragma unroll
                for (int dc = 0; dc < 3; dc++) {
                    int cc = c - dc;
                    if (cc >= 0 && (cc & 1) == 0) {
                        int pc = cc >> 1;
                        v += ek[(((pr * 32 + pc) * 9) + dr * 3 + dc) * GATE + n];
                    }
                }
            }
        }
    } else if (row < PIX + UNITS) {
        v = er[(row - PIX) * GATE + n];
    } else {
        int u = row - PIX - UNITS;
        v = ek[(9216 + u) * GATE + n] + ek[(9472 + u) * GATE + n];
    }
    __nv_bfloat16 hi, lo; split_bf16(v, hi, lo);
    g_Be[(size_t)row * GATE + n]               = hi;
    g_Be[(size_t)(K_ENC + row) * GATE + n]     = lo;
    g_Be[(size_t)(2 * K_ENC + row) * GATE + n] = hi;
}

__global__ void build_w2c_kernel(const float* __restrict__ dk, const float* __restrict__ dr,
                                 const float* __restrict__ wd) {
    int idx = blockIdx.x * blockDim.x + threadIdx.x;
    if (idx < K_DEC * GATE) {
        int row = idx / GATE;
        int n   = idx - row * GATE;
        float v = (row < UNITS) ? dk[row * GATE + n] : dr[(row - UNITS) * GATE + n];
        __nv_bfloat16 hi, lo; split_bf16(v, hi, lo);
        g_Bd[row * GATE + n]               = hi;
        g_Bd[(K_DEC + row) * GATE + n]     = lo;
        g_Bd[(2 * K_DEC + row) * GATE + n] = hi;
    }
    int j = idx - K_DEC * GATE;
    if (j >= 0 && j < K_CAN * PIX) {
        int row = j / PIX;
        int n   = j - row * PIX;
        float v = wd[j];
        __nv_bfloat16 hi, lo; split_bf16(v, hi, lo);
        g_Bc[row * PIX + n]               = hi;
        g_Bc[(K_CAN + row) * PIX + n]     = lo;
        g_Bc[(2 * K_CAN + row) * PIX + n] = hi;
    }
}

__global__ void init_xhat_kernel(const float* __restrict__ x, float* __restrict__ canvas) {
    int i = blockIdx.x * blockDim.x + threadIdx.x;
    canvas[i] = 0.f;
    {
        int b = i >> 12, p = i & (PIX - 1);
        float v = x[i] - 0.5f;
        __nv_bfloat16 hi, lo; split_bf16(v, hi, lo);
        size_t base = (size_t)b * KP_ENC + p;
        g_Aeb[base]             = hi;
        g_Aeb[base + K_ENC]     = hi;
        g_Aeb[base + 2 * K_ENC] = lo;
    }
    if (i < BATCH * UNITS) { g_ce[i] = 0.f; g_cd[i] = 0.f; }
    if (i < BATCH * 3 * 2 * UNITS) {
        int b = i / (3 * 2 * UNITS);
        int r = i - b * (3 * 2 * UNITS);
        int seg = r / (2 * UNITS), off = r - seg * (2 * UNITS);
        g_Aeb[(size_t)b * KP_ENC + seg * K_ENC + PIX + off] = __float2bfloat16(0.f);
    }
    if (i < BATCH * 3 * UNITS) {
        int b = i / (3 * UNITS);
        int r = i - b * (3 * UNITS);
        int seg = r / UNITS, off = r - seg * UNITS;
        g_Adb[(size_t)b * KP_DEC + seg * K_DEC + UNITS + off] = __float2bfloat16(0.f);
    }
}

// ---------------- fused enc LSTM (split reduce) + attention ----------------
__global__ void lstm_enc_attn_kernel(const float* __restrict__ part,
                                     const float* __restrict__ bias,
                                     const float* __restrict__ Wenc,
                                     const float* __restrict__ benc) {
    const int b = blockIdx.x;
    const int u = threadIdx.x;
    __shared__ float sh[UNITS];
    __shared__ float lg[10];
    __shared__ float attn[10];

    float gi = bias[u], gf = bias[UNITS + u], gg = bias[2 * UNITS + u], go = bias[3 * UNITS + u];
    const size_t roff = (size_t)b * GATE + u;
    #pragma unroll
    for (int s = 0; s < ENC_SPLITS; s++) {
        const float* p = part + (size_t)s * (BATCH * GATE) + roff;
        gi += p[0]; gf += p[UNITS]; gg += p[2 * UNITS]; go += p[3 * UNITS];
    }
    int idx = b * UNITS + u;
    float cn = sigmoidf(gf) * g_ce[idx] + sigmoidf(gi) * tanhf(gg);
    float hn = sigmoidf(go) * tanhf(cn);
    g_ce[idx] = cn;
    sh[u] = hn;
    {
        __nv_bfloat16 hi, lo; split_bf16(hn, hi, lo);
        size_t base = (size_t)b * KP_ENC + PIX + u;
        g_Aeb[base]             = hi;
        g_Aeb[base + K_ENC]     = hi;
        g_Aeb[base + 2 * K_ENC] = lo;
    }
    if (u < 10) lg[u] = benc[u];
    __syncthreads();

    float p10[10];
    float hv = sh[u];
    #pragma unroll
    for (int j = 0; j < 10; j++) p10[j] = hv * Wenc[u * 10 + j];
    #pragma unroll
    for (int j = 0; j < 10; j++)
        #pragma unroll
        for (int off = 16; off > 0; off >>= 1)
            p10[j] += __shfl_down_sync(0xffffffffu, p10[j], off);
    if ((u & 31) == 0)
        for (int j = 0; j < 10; j++) atomicAdd(&lg[j], p10[j]);
    __syncthreads();
    if (u == 0) {
        float m = lg[0];
        for (int j = 1; j < 10; j++) m = fmaxf(m, lg[j]);
        float ssum = 0.f, e[10];
        for (int j = 0; j < 10; j++) { e[j] = expf(lg[j] - m); ssum += e[j]; }
        float inv = 1.f / ssum;
        for (int j = 0; j < 10; j++) attn[j] = e[j] * inv;
    }
    __syncthreads();
    float zacc = 0.f;
    #pragma unroll
    for (int j = 0; j < 10; j++) zacc += attn[j] * Wenc[u * 10 + j];
    __nv_bfloat16 hi, lo; split_bf16(zacc, hi, lo);
    size_t bd = (size_t)b * KP_DEC + u;
    g_Adb[bd]             = hi;
    g_Adb[bd + K_DEC]     = hi;
    g_Adb[bd + 2 * K_DEC] = lo;
}

// ---------------- dec LSTM (split reduce) ----------------
__global__ void lstm_dec_kernel(const float* __restrict__ part, const float* __restrict__ bias) {
    int idx = blockIdx.x * blockDim.x + threadIdx.x;
    int b = idx / UNITS, u = idx - b * UNITS;
    float gi = bias[u], gf = bias[UNITS + u], gg = bias[2 * UNITS + u], go = bias[3 * UNITS + u];
    size_t roff = (size_t)b * GATE + u;
    #pragma unroll
    for (int s = 0; s < DEC_SPLITS; s++) {
        const float* p = part + (size_t)s * (BATCH * GATE) + roff;
        gi += p[0]; gf += p[UNITS]; gg += p[2 * UNITS]; go += p[3 * UNITS];
    }
    float cn = sigmoidf(gf) * g_cd[idx] + sigmoidf(gi) * tanhf(gg);
    float hn = sigmoidf(go) * tanhf(cn);
    g_cd[idx] = cn;
    __nv_bfloat16 hi, lo; split_bf16(hn, hi, lo);
    size_t be = (size_t)b * KP_ENC + PIX + UNITS + u;
    g_Aeb[be]             = hi;
    g_Aeb[be + K_ENC]     = hi;
    g_Aeb[be + 2 * K_ENC] = lo;
    size_t bd = (size_t)b * KP_DEC + UNITS + u;
    g_Adb[bd]             = hi;
    g_Adb[bd + K_DEC]     = hi;
    g_Adb[bd + 2 * K_DEC] = lo;
    size_t bc = (size_t)b * KP_CAN + u;
    g_Acb[bc]             = hi;
    g_Acb[bc + K_CAN]     = hi;
    g_Acb[bc + 2 * K_CAN] = lo;
}

// ---------------- launcher ----------------
extern "C" void kernel_launch(void* const* d_in, const int* in_sizes, int n_in,
                              void* d_out, int out_size) {
    const float* x          = (const float*)d_in[0];
    const float* enc_kernel = (const float*)d_in[1];
    const float* enc_rec    = (const float*)d_in[2];
    const float* enc_bias   = (const float*)d_in[3];
    const float* dec_kernel = (const float*)d_in[4];
    const float* dec_rec    = (const float*)d_in[5];
    const float* dec_bias   = (const float*)d_in[6];
    const float* W_enc      = (const float*)d_in[7];
    const float* b_enc      = (const float*)d_in[8];
    const float* W_dec      = (const float*)d_in[9];
    const float* b_dec      = (const float*)d_in[10];
    float* canvas = (float*)d_out;

    __nv_bfloat16 *Ae, *Ad, *Ac, *Be, *Bd, *Bc;
    float *part;
    cudaGetSymbolAddress((void**)&Ae,  g_Aeb);
    cudaGetSymbolAddress((void**)&Ad,  g_Adb);
    cudaGetSymbolAddress((void**)&Ac,  g_Acb);
    cudaGetSymbolAddress((void**)&Be,  g_Be);
    cudaGetSymbolAddress((void**)&Bd,  g_Bd);
    cudaGetSymbolAddress((void**)&Bc,  g_Bc);
    cudaGetSymbolAddress((void**)&part, g_part);

    cudaFuncSetAttribute(gemm_hmma<0>, cudaFuncAttributeMaxDynamicSharedMemorySize, GEMM_SMEM);
    cudaFuncSetAttribute(gemm_hmma<1>, cudaFuncAttributeMaxDynamicSharedMemorySize, GEMM_SMEM);

    // ---- setup: exactly 3 launches (enc GEMM stays in the ncu -s 5 slot) ----
    build_w1_kernel<<<(K_ENC * GATE + 255) / 256, 256>>>(enc_kernel, enc_rec);
    build_w2c_kernel<<<(K_DEC * GATE + K_CAN * PIX + 255) / 256, 256>>>(dec_kernel, dec_rec, W_dec);
    init_xhat_kernel<<<(BATCH * PIX) / 256, 256>>>(x, canvas);

    // ---- 10 sequential DRAW steps ----
    for (int t = 0; t < STEPS; t++) {
        gemm_hmma<0><<<dim3(GATE / 128, BATCH / CTA_M, ENC_SPLITS), 128, GEMM_SMEM>>>(
            Ae, KP_ENC, Be, GATE, part, GATE, KP_ENC / ENC_SPLITS, nullptr, nullptr, nullptr);

        lstm_enc_attn_kernel<<<BATCH, 256>>>(part, enc_bias, W_enc, b_enc);

        gemm_hmma<0><<<dim3(GATE / 128, BATCH / CTA_M, DEC_SPLITS), 128, GEMM_SMEM>>>(
            Ad, KP_DEC, Bd, GATE, part, GATE, KP_DEC / DEC_SPLITS, nullptr, nullptr, nullptr);

        lstm_dec_kernel<<<(BATCH * UNITS) / 256, 256>>>(part, dec_bias);

        gemm_hmma<1><<<dim3(PIX / 128, BATCH / CTA_M, 1), 128, GEMM_SMEM>>>(
            Ac, KP_CAN, Bc, PIX, canvas, PIX, KP_CAN, b_dec, x, Ae);
    }
}

// round 13
// speedup vs baseline: 1.0524x; 1.0524x over previous
#include <cuda_runtime.h>
#include <cuda_bf16.h>
#include <math.h>
#include <stdint.h>

// ---------------- problem constants ----------------
#define IMGD   64
#define BATCH  512
#define UNITS  256
#define STEPS  10
#define GATE   (4*UNITS)          // 1024
#define PIX    (IMGD*IMGD)        // 4096
#define K_ENC  (PIX + 2*UNITS)    // 4608
#define K_DEC  (2*UNITS)          // 512
#define K_CAN  UNITS              // 256
#define KP_ENC (3*K_ENC)          // 13824
#define KP_DEC (3*K_DEC)          // 1536
#define KP_CAN (3*K_CAN)          // 768

#define ENC_SPLITS 9              // grid (8,4,9) = 288 CTAs @ 2/SM ~ 1 wave
#define DEC_SPLITS 8              // grid (8,4,8) = 256 CTAs

// ---------------- scratch (device globals) ----------------
__device__ __align__(16) __nv_bfloat16 g_Be[(size_t)KP_ENC * GATE];
__device__ __align__(16) __nv_bfloat16 g_Bd[(size_t)KP_DEC * GATE];
__device__ __align__(16) __nv_bfloat16 g_Bc[(size_t)KP_CAN * PIX];
__device__ __align__(16) __nv_bfloat16 g_Aeb[(size_t)BATCH * KP_ENC];
__device__ __align__(16) __nv_bfloat16 g_Adb[(size_t)BATCH * KP_DEC];
__device__ __align__(16) __nv_bfloat16 g_Acb[(size_t)BATCH * KP_CAN];
__device__ __align__(16) float g_part[(size_t)ENC_SPLITS * BATCH * GATE];
__device__ __align__(16) float g_ce[BATCH * UNITS];
__device__ __align__(16) float g_cd[BATCH * UNITS];

__device__ __forceinline__ float sigmoidf(float x) { return 1.f / (1.f + expf(-x)); }
__device__ __forceinline__ void split_bf16(float v, __nv_bfloat16& hi, __nv_bfloat16& lo) {
    hi = __float2bfloat16(v);
    lo = __float2bfloat16(v - __bfloat162float(hi));
}

// ---------------- PTX helpers ----------------
__device__ __forceinline__ uint32_t smem_u32(const void* p) {
    uint32_t a;
    asm("{ .reg .u64 t; cvta.to.shared.u64 t, %1; cvt.u32.u64 %0, t; }" : "=r"(a) : "l"(p));
    return a;
}
#define CP_ASYNC16(dst, src) \
    asm volatile("cp.async.cg.shared.global [%0], [%1], 16;\n" :: "r"(dst), "l"(src))
#define CP_COMMIT() asm volatile("cp.async.commit_group;\n")

__device__ __forceinline__ void ldmatrix_x4_a(uint32_t* r, uint32_t a) {
    asm volatile("ldmatrix.sync.aligned.m8n8.x4.shared.b16 {%0,%1,%2,%3}, [%4];\n"
                 : "=r"(r[0]), "=r"(r[1]), "=r"(r[2]), "=r"(r[3]) : "r"(a));
}
__device__ __forceinline__ void ldmatrix_x4_t(uint32_t* r, uint32_t a) {
    asm volatile("ldmatrix.sync.aligned.m8n8.x4.trans.shared.b16 {%0,%1,%2,%3}, [%4];\n"
                 : "=r"(r[0]), "=r"(r[1]), "=r"(r[2]), "=r"(r[3]) : "r"(a));
}
__device__ __forceinline__ void mma_bf16(float* d, const uint32_t* a, uint32_t b0, uint32_t b1) {
    asm volatile("mma.sync.aligned.m16n8k16.row.col.f32.bf16.bf16.f32 "
                 "{%0,%1,%2,%3}, {%4,%5,%6,%7}, {%8,%9}, {%0,%1,%2,%3};\n"
                 : "+f"(d[0]), "+f"(d[1]), "+f"(d[2]), "+f"(d[3])
                 : "r"(a[0]), "r"(a[1]), "r"(a[2]), "r"(a[3]), "r"(b0), "r"(b1));
}

// ---------------- HMMA GEMM: 128x128 CTA, 4 warps (2x2 of 64x64), BK=32, 4 stages, 2 CTA/SM ----
// 64x64 warp tile: per k16-step 8 LDSM : 32 HMMA (halved LDSM issue cost per MMA).
#define A_ROW_B 80                 // 32*2 + 16 pad
#define B_ROW_B 272                // 128*2 + 16 pad
#define STG_BYTES (128 * A_ROW_B + 32 * B_ROW_B)   // 10240 + 8704 = 18944
#define GEMM_SMEM (4 * STG_BYTES)                  // 75776

template<int MODE>
__global__ void __launch_bounds__(128, 2) gemm_hmma(
    const __nv_bfloat16* __restrict__ A, int lda,
    const __nv_bfloat16* __restrict__ B, int ldb,
    float* __restrict__ out, int ldc, int kPerSplit,
    const float* __restrict__ bias,
    const float* __restrict__ x, __nv_bfloat16* __restrict__ aeb)
{
    extern __shared__ __align__(16) char sm[];
    const int tid  = threadIdx.x;
    const int m0   = blockIdx.y * 128;
    const int n0   = blockIdx.x * 128;
    const int z    = blockIdx.z;
    const int kbase = z * kPerSplit;
    const int S    = kPerSplit / 32;
    const int warp = tid >> 5, lane = tid & 31;
    const int wm   = (warp >> 1) * 64;   // 2 warp-rows of 64
    const int wn   = (warp & 1) * 64;    // 2 warp-cols of 64

    // hoisted lane-dependent smem offsets
    const uint32_t smbase = smem_u32(sm);
    const uint32_t a_lane = (uint32_t)((wm + (lane & 15)) * A_ROW_B + (lane >> 4) * 16);
    const uint32_t b_lane = (uint32_t)(128 * A_ROW_B + (lane & 15) * B_ROW_B
                                       + (wn + (lane >> 4) * 8) * 2);

    auto prefetch = [&](int s) {
        uint32_t st = smbase + (uint32_t)((s & 3) * STG_BYTES);
        const int k0 = kbase + s * 32;
        #pragma unroll
        for (int i = 0; i < 4; i++) {          // A: 128 x 32 (512 chunks / 128 thr)
            int c = tid + 128 * i;
            int row = c >> 2, col = (c & 3) * 8;
            CP_ASYNC16(st + (uint32_t)(row * A_ROW_B + col * 2),
                       A + (size_t)(m0 + row) * lda + k0 + col);
        }
        #pragma unroll
        for (int i = 0; i < 4; i++) {          // B: 32 x 128 (512 chunks / 128 thr)
            int c = tid + 128 * i;
            int row = c >> 4, col = (c & 15) * 8;
            CP_ASYNC16(st + (uint32_t)(128 * A_ROW_B + row * B_ROW_B + col * 2),
                       B + (size_t)(k0 + row) * ldb + n0 + col);
        }
        CP_COMMIT();
    };

    float acc[4][8][4] = {};
    prefetch(0); prefetch(1); prefetch(2);

    for (int s = 0; s < S; s++) {
        int rem = S - 1 - s;
        if (rem >= 2)      asm volatile("cp.async.wait_group 2;\n" ::: "memory");
        else if (rem == 1) asm volatile("cp.async.wait_group 1;\n" ::: "memory");
        else               asm volatile("cp.async.wait_group 0;\n" ::: "memory");
        __syncthreads();
        if (s + 3 < S) prefetch(s + 3);

        const uint32_t st = smbase + (uint32_t)((s & 3) * STG_BYTES);
        const uint32_t a0 = st + a_lane;
        const uint32_t b0a = st + b_lane;
        #pragma unroll
        for (int kk = 0; kk < 32; kk += 16) {
            uint32_t af[4][4], bfr[4][4];
            #pragma unroll
            for (int mt = 0; mt < 4; mt++)
                ldmatrix_x4_a(af[mt], a0 + (uint32_t)(mt * 16 * A_ROW_B + kk * 2));
            #pragma unroll
            for (int g = 0; g < 4; g++)
                ldmatrix_x4_t(bfr[g], b0a + (uint32_t)(kk * B_ROW_B + g * 32));
            #pragma unroll
            for (int mt = 0; mt < 4; mt++)
                #pragma unroll
                for (int nt = 0; nt < 8; nt++)
                    mma_bf16(acc[mt][nt], af[mt],
                             bfr[nt >> 1][(nt & 1) * 2], bfr[nt >> 1][(nt & 1) * 2 + 1]);
        }
    }

    if (MODE == 0) {
        float* o = out + (size_t)z * (BATCH * ldc);
        #pragma unroll
        for (int mt = 0; mt < 4; mt++) {
            #pragma unroll
            for (int nt = 0; nt < 8; nt++) {
                int r = m0 + wm + mt * 16 + (lane >> 2);
                int c = n0 + wn + nt * 8 + (lane & 3) * 2;
                *reinterpret_cast<float2*>(&o[(size_t)r * ldc + c]) =
                    make_float2(acc[mt][nt][0], acc[mt][nt][1]);
                *reinterpret_cast<float2*>(&o[(size_t)(r + 8) * ldc + c]) =
                    make_float2(acc[mt][nt][2], acc[mt][nt][3]);
            }
        }
    } else {
        #pragma unroll
        for (int mt = 0; mt < 4; mt++) {
            #pragma unroll
            for (int nt = 0; nt < 8; nt++) {
                int c = n0 + wn + nt * 8 + (lane & 3) * 2;
                float b0 = bias[c], b1 = bias[c + 1];
                #pragma unroll
                for (int pr = 0; pr < 2; pr++) {
                    int r = m0 + wm + mt * 16 + (lane >> 2) + 8 * pr;
                    size_t o = (size_t)r * ldc + c;
                    float2 old = *reinterpret_cast<const float2*>(&out[o]);
                    float v0 = acc[mt][nt][2 * pr]     + old.x + b0;
                    float v1 = acc[mt][nt][2 * pr + 1] + old.y + b1;
                    *reinterpret_cast<float2*>(&out[o]) = make_float2(v0, v1);
                    float xv0 = x[o] - sigmoidf(v0);
                    float xv1 = x[o + 1] - sigmoidf(v1);
                    __nv_bfloat16 h0, l0, h1, l1;
                    split_bf16(xv0, h0, l0);
                    split_bf16(xv1, h1, l1);
                    size_t ab = (size_t)r * KP_ENC + c;
                    aeb[ab]             = h0; aeb[ab + 1]             = h1;
                    aeb[ab + K_ENC]     = h0; aeb[ab + K_ENC + 1]     = h1;
                    aeb[ab + 2 * K_ENC] = l0; aeb[ab + 2 * K_ENC + 1] = l1;
                }
            }
        }
    }
}

// ---------------- setup kernels (exactly 3 launches; harness adds 2 before) ----
__global__ void build_w1_kernel(const float* __restrict__ ek, const float* __restrict__ er) {
    int idx = blockIdx.x * blockDim.x + threadIdx.x;
    if (idx >= K_ENC * GATE) return;
    int row = idx / GATE;
    int n   = idx - row * GATE;
    float v;
    if (row < PIX) {
        int r = row >> 6, c = row & 63;
        v = 0.f;
        #pragma unroll
        for (int dr = 0; dr < 3; dr++) {
            int rr = r - dr;
            if (rr >= 0 && (rr & 1) == 0) {
                int pr = rr >> 1;
                #pragma unroll
                for (int dc = 0; dc < 3; dc++) {
                    int cc = c - dc;
                    if (cc >= 0 && (cc & 1) == 0) {
                        int pc = cc >> 1;
                        v += ek[(((pr * 32 + pc) * 9) + dr * 3 + dc) * GATE + n];
                    }
                }
            }
        }
    } else if (row < PIX + UNITS) {
        v = er[(row - PIX) * GATE + n];
    } else {
        int u = row - PIX - UNITS;
        v = ek[(9216 + u) * GATE + n] + ek[(9472 + u) * GATE + n];
    }
    __nv_bfloat16 hi, lo; split_bf16(v, hi, lo);
    g_Be[(size_t)row * GATE + n]               = hi;
    g_Be[(size_t)(K_ENC + row) * GATE + n]     = lo;
    g_Be[(size_t)(2 * K_ENC + row) * GATE + n] = hi;
}

__global__ void build_w2c_kernel(const float* __restrict__ dk, const float* __restrict__ dr,
                                 const float* __restrict__ wd) {
    int idx = blockIdx.x * blockDim.x + threadIdx.x;
    if (idx < K_DEC * GATE) {
        int row = idx / GATE;
        int n   = idx - row * GATE;
        float v = (row < UNITS) ? dk[row * GATE + n] : dr[(row - UNITS) * GATE + n];
        __nv_bfloat16 hi, lo; split_bf16(v, hi, lo);
        g_Bd[row * GATE + n]               = hi;
        g_Bd[(K_DEC + row) * GATE + n]     = lo;
        g_Bd[(2 * K_DEC + row) * GATE + n] = hi;
    }
    int j = idx - K_DEC * GATE;
    if (j >= 0 && j < K_CAN * PIX) {
        int row = j / PIX;
        int n   = j - row * PIX;
        float v = wd[j];
        __nv_bfloat16 hi, lo; split_bf16(v, hi, lo);
        g_Bc[row * PIX + n]               = hi;
        g_Bc[(K_CAN + row) * PIX + n]     = lo;
        g_Bc[(2 * K_CAN + row) * PIX + n] = hi;
    }
}

__global__ void init_xhat_kernel(const float* __restrict__ x, float* __restrict__ canvas) {
    int i = blockIdx.x * blockDim.x + threadIdx.x;
    canvas[i] = 0.f;
    {
        int b = i >> 12, p = i & (PIX - 1);
        float v = x[i] - 0.5f;
        __nv_bfloat16 hi, lo; split_bf16(v, hi, lo);
        size_t base = (size_t)b * KP_ENC + p;
        g_Aeb[base]             = hi;
        g_Aeb[base + K_ENC]     = hi;
        g_Aeb[base + 2 * K_ENC] = lo;
    }
    if (i < BATCH * UNITS) { g_ce[i] = 0.f; g_cd[i] = 0.f; }
    if (i < BATCH * 3 * 2 * UNITS) {
        int b = i / (3 * 2 * UNITS);
        int r = i - b * (3 * 2 * UNITS);
        int seg = r / (2 * UNITS), off = r - seg * (2 * UNITS);
        g_Aeb[(size_t)b * KP_ENC + seg * K_ENC + PIX + off] = __float2bfloat16(0.f);
    }
    if (i < BATCH * 3 * UNITS) {
        int b = i / (3 * UNITS);
        int r = i - b * (3 * UNITS);
        int seg = r / UNITS, off = r - seg * UNITS;
        g_Adb[(size_t)b * KP_DEC + seg * K_DEC + UNITS + off] = __float2bfloat16(0.f);
    }
}

// ---------------- fused enc LSTM (split reduce) + attention ----------------
__global__ void lstm_enc_attn_kernel(const float* __restrict__ part,
                                     const float* __restrict__ bias,
                                     const float* __restrict__ Wenc,
                                     const float* __restrict__ benc) {
    const int b = blockIdx.x;
    const int u = threadIdx.x;
    __shared__ float sh[UNITS];
    __shared__ float lg[10];
    __shared__ float attn[10];

    float gi = bias[u], gf = bias[UNITS + u], gg = bias[2 * UNITS + u], go = bias[3 * UNITS + u];
    const size_t roff = (size_t)b * GATE + u;
    #pragma unroll
    for (int s = 0; s < ENC_SPLITS; s++) {
        const float* p = part + (size_t)s * (BATCH * GATE) + roff;
        gi += p[0]; gf += p[UNITS]; gg += p[2 * UNITS]; go += p[3 * UNITS];
    }
    int idx = b * UNITS + u;
    float cn = sigmoidf(gf) * g_ce[idx] + sigmoidf(gi) * tanhf(gg);
    float hn = sigmoidf(go) * tanhf(cn);
    g_ce[idx] = cn;
    sh[u] = hn;
    {
        __nv_bfloat16 hi, lo; split_bf16(hn, hi, lo);
        size_t base = (size_t)b * KP_ENC + PIX + u;
        g_Aeb[base]             = hi;
        g_Aeb[base + K_ENC]     = hi;
        g_Aeb[base + 2 * K_ENC] = lo;
    }
    if (u < 10) lg[u] = benc[u];
    __syncthreads();

    float p10[10];
    float hv = sh[u];
    #pragma unroll
    for (int j = 0; j < 10; j++) p10[j] = hv * Wenc[u * 10 + j];
    #pragma unroll
    for (int j = 0; j < 10; j++)
        #pragma unroll
        for (int off = 16; off > 0; off >>= 1)
            p10[j] += __shfl_down_sync(0xffffffffu, p10[j], off);
    if ((u & 31) == 0)
        for (int j = 0; j < 10; j++) atomicAdd(&lg[j], p10[j]);
    __syncthreads();
    if (u == 0) {
        float m = lg[0];
        for (int j = 1; j < 10; j++) m = fmaxf(m, lg[j]);
        float ssum = 0.f, e[10];
        for (int j = 0; j < 10; j++) { e[j] = expf(lg[j] - m); ssum += e[j]; }
        float inv = 1.f / ssum;
        for (int j = 0; j < 10; j++) attn[j] = e[j] * inv;
    }
    __syncthreads();
    float zacc = 0.f;
    #pragma unroll
    for (int j = 0; j < 10; j++) zacc += attn[j] * Wenc[u * 10 + j];
    __nv_bfloat16 hi, lo; split_bf16(zacc, hi, lo);
    size_t bd = (size_t)b * KP_DEC + u;
    g_Adb[bd]             = hi;
    g_Adb[bd + K_DEC]     = hi;
    g_Adb[bd + 2 * K_DEC] = lo;
}

// ---------------- dec LSTM (split reduce) ----------------
__global__ void lstm_dec_kernel(const float* __restrict__ part, const float* __restrict__ bias) {
    int idx = blockIdx.x * blockDim.x + threadIdx.x;
    int b = idx / UNITS, u = idx - b * UNITS;
    float gi = bias[u], gf = bias[UNITS + u], gg = bias[2 * UNITS + u], go = bias[3 * UNITS + u];
    size_t roff = (size_t)b * GATE + u;
    #pragma unroll
    for (int s = 0; s < DEC_SPLITS; s++) {
        const float* p = part + (size_t)s * (BATCH * GATE) + roff;
        gi += p[0]; gf += p[UNITS]; gg += p[2 * UNITS]; go += p[3 * UNITS];
    }
    float cn = sigmoidf(gf) * g_cd[idx] + sigmoidf(gi) * tanhf(gg);
    float hn = sigmoidf(go) * tanhf(cn);
    g_cd[idx] = cn;
    __nv_bfloat16 hi, lo; split_bf16(hn, hi, lo);
    size_t be = (size_t)b * KP_ENC + PIX + UNITS + u;
    g_Aeb[be]             = hi;
    g_Aeb[be + K_ENC]     = hi;
    g_Aeb[be + 2 * K_ENC] = lo;
    size_t bd = (size_t)b * KP_DEC + UNITS + u;
    g_Adb[bd]             = hi;
    g_Adb[bd + K_DEC]     = hi;
    g_Adb[bd + 2 * K_DEC] = lo;
    size_t bc = (size_t)b * KP_CAN + u;
    g_Acb[bc]             = hi;
    g_Acb[bc + K_CAN]     = hi;
    g_Acb[bc + 2 * K_CAN] = lo;
}

// ---------------- launcher ----------------
extern "C" void kernel_launch(void* const* d_in, const int* in_sizes, int n_in,
                              void* d_out, int out_size) {
    const float* x          = (const float*)d_in[0];
    const float* enc_kernel = (const float*)d_in[1];
    const float* enc_rec    = (const float*)d_in[2];
    const float* enc_bias   = (const float*)d_in[3];
    const float* dec_kernel = (const float*)d_in[4];
    const float* dec_rec    = (const float*)d_in[5];
    const float* dec_bias   = (const float*)d_in[6];
    const float* W_enc      = (const float*)d_in[7];
    const float* b_enc      = (const float*)d_in[8];
    const float* W_dec      = (const float*)d_in[9];
    const float* b_dec      = (const float*)d_in[10];
    float* canvas = (float*)d_out;

    __nv_bfloat16 *Ae, *Ad, *Ac, *Be, *Bd, *Bc;
    float *part;
    cudaGetSymbolAddress((void**)&Ae,  g_Aeb);
    cudaGetSymbolAddress((void**)&Ad,  g_Adb);
    cudaGetSymbolAddress((void**)&Ac,  g_Acb);
    cudaGetSymbolAddress((void**)&Be,  g_Be);
    cudaGetSymbolAddress((void**)&Bd,  g_Bd);
    cudaGetSymbolAddress((void**)&Bc,  g_Bc);
    cudaGetSymbolAddress((void**)&part, g_part);

    cudaFuncSetAttribute(gemm_hmma<0>, cudaFuncAttributeMaxDynamicSharedMemorySize, GEMM_SMEM);
    cudaFuncSetAttribute(gemm_hmma<1>, cudaFuncAttributeMaxDynamicSharedMemorySize, GEMM_SMEM);

    // ---- setup: exactly 3 launches (enc GEMM stays in the ncu -s 5 slot) ----
    build_w1_kernel<<<(K_ENC * GATE + 255) / 256, 256>>>(enc_kernel, enc_rec);
    build_w2c_kernel<<<(K_DEC * GATE + K_CAN * PIX + 255) / 256, 256>>>(dec_kernel, dec_rec, W_dec);
    init_xhat_kernel<<<(BATCH * PIX) / 256, 256>>>(x, canvas);

    // ---- 10 sequential DRAW steps ----
    for (int t = 0; t < STEPS; t++) {
        gemm_hmma<0><<<dim3(GATE / 128, BATCH / 128, ENC_SPLITS), 128, GEMM_SMEM>>>(
            Ae, KP_ENC, Be, GATE, part, GATE, KP_ENC / ENC_SPLITS, nullptr, nullptr, nullptr);

        lstm_enc_attn_kernel<<<BATCH, 256>>>(part, enc_bias, W_enc, b_enc);

        gemm_hmma<0><<<dim3(GATE / 128, BATCH / 128, DEC_SPLITS), 128, GEMM_SMEM>>>(
            Ad, KP_DEC, Bd, GATE, part, GATE, KP_DEC / DEC_SPLITS, nullptr, nullptr, nullptr);

        lstm_dec_kernel<<<(BATCH * UNITS) / 256, 256>>>(part, dec_bias);

        gemm_hmma<1><<<dim3(PIX / 128, BATCH / 128, 1), 128, GEMM_SMEM>>>(
            Ac, KP_CAN, Bc, PIX, canvas, PIX, KP_CAN, b_dec, x, Ae);
    }
}

// round 14
// speedup vs baseline: 1.1037x; 1.0487x over previous
#include <cuda_runtime.h>
#include <cuda_bf16.h>
#include <math.h>
#include <stdint.h>

// ---------------- problem constants ----------------
#define IMGD   64
#define BATCH  512
#define UNITS  256
#define STEPS  10
#define GATE   (4*UNITS)          // 1024
#define PIX    (IMGD*IMGD)        // 4096
#define K_ENC  (PIX + 2*UNITS)    // 4608
#define K_DEC  (2*UNITS)          // 512
#define K_CAN  UNITS              // 256
#define KP_ENC (3*K_ENC)          // 13824
#define KP_DEC (3*K_DEC)          // 1536
#define KP_CAN (3*K_CAN)          // 768

#define ENC_SPLITS 9              // grid (8,4,9) = 288 CTAs @ 2/SM ~ 1 wave; K/split = 1536 = 24 k64-iters
#define DEC_SPLITS 8              // grid (8,4,8) = 256 CTAs; K/split = 192 = 3 k64-iters

// ---------------- scratch (device globals) ----------------
__device__ __align__(16) __nv_bfloat16 g_Be[(size_t)KP_ENC * GATE];
__device__ __align__(16) __nv_bfloat16 g_Bd[(size_t)KP_DEC * GATE];
__device__ __align__(16) __nv_bfloat16 g_Bc[(size_t)KP_CAN * PIX];
__device__ __align__(16) __nv_bfloat16 g_Aeb[(size_t)BATCH * KP_ENC];
__device__ __align__(16) __nv_bfloat16 g_Adb[(size_t)BATCH * KP_DEC];
__device__ __align__(16) __nv_bfloat16 g_Acb[(size_t)BATCH * KP_CAN];
__device__ __align__(16) float g_part[(size_t)ENC_SPLITS * BATCH * GATE];
__device__ __align__(16) float g_ce[BATCH * UNITS];
__device__ __align__(16) float g_cd[BATCH * UNITS];

__device__ __forceinline__ float sigmoidf(float x) { return 1.f / (1.f + expf(-x)); }
__device__ __forceinline__ void split_bf16(float v, __nv_bfloat16& hi, __nv_bfloat16& lo) {
    hi = __float2bfloat16(v);
    lo = __float2bfloat16(v - __bfloat162float(hi));
}

// ---------------- PTX helpers ----------------
__device__ __forceinline__ uint32_t smem_u32(const void* p) {
    uint32_t a;
    asm("{ .reg .u64 t; cvta.to.shared.u64 t, %1; cvt.u32.u64 %0, t; }" : "=r"(a) : "l"(p));
    return a;
}
#define CP_ASYNC16(dst, src) \
    asm volatile("cp.async.cg.shared.global [%0], [%1], 16;\n" :: "r"(dst), "l"(src))
#define CP_COMMIT() asm volatile("cp.async.commit_group;\n")

__device__ __forceinline__ void ldmatrix_x4_a(uint32_t* r, uint32_t a) {
    asm volatile("ldmatrix.sync.aligned.m8n8.x4.shared.b16 {%0,%1,%2,%3}, [%4];\n"
                 : "=r"(r[0]), "=r"(r[1]), "=r"(r[2]), "=r"(r[3]) : "r"(a));
}
__device__ __forceinline__ void ldmatrix_x4_t(uint32_t* r, uint32_t a) {
    asm volatile("ldmatrix.sync.aligned.m8n8.x4.trans.shared.b16 {%0,%1,%2,%3}, [%4];\n"
                 : "=r"(r[0]), "=r"(r[1]), "=r"(r[2]), "=r"(r[3]) : "r"(a));
}
__device__ __forceinline__ void mma_bf16(float* d, const uint32_t* a, uint32_t b0, uint32_t b1) {
    asm volatile("mma.sync.aligned.m16n8k16.row.col.f32.bf16.bf16.f32 "
                 "{%0,%1,%2,%3}, {%4,%5,%6,%7}, {%8,%9}, {%0,%1,%2,%3};\n"
                 : "+f"(d[0]), "+f"(d[1]), "+f"(d[2]), "+f"(d[3])
                 : "r"(a[0]), "r"(a[1]), "r"(a[2]), "r"(a[3]), "r"(b0), "r"(b1));
}

// ---------------- HMMA GEMM: CTA_M x 128 tile, 4 warps (2x2), BK=64, 3 stages, 2 CTA/SM ----
// Warp tile (CTA_M/2) x 64. CTA_M=128 for enc/dec (validated 64x64 warp tile),
// CTA_M=64 for canvas (256-CTA grid + epilogue parallelism).
#define A_ROW_B 144                // 64*2 + 16 pad  (9i mod 8 distinct -> LDSM conflict-free)
#define B_ROW_B 272                // 128*2 + 16 pad (17i mod 8 distinct)

template<int CTA_M, int MODE>
__global__ void __launch_bounds__(128, 2) gemm_hmma(
    const __nv_bfloat16* __restrict__ A, int lda,
    const __nv_bfloat16* __restrict__ B, int ldb,
    float* __restrict__ out, int ldc, int kPerSplit,
    const float* __restrict__ bias,
    const float* __restrict__ x, __nv_bfloat16* __restrict__ aeb)
{
    constexpr int MT  = CTA_M / 32;                       // acc m-tiles per warp
    constexpr int STG = CTA_M * A_ROW_B + 64 * B_ROW_B;   // stage bytes

    extern __shared__ __align__(16) char sm[];
    const int tid  = threadIdx.x;
    const int m0   = blockIdx.y * CTA_M;
    const int n0   = blockIdx.x * 128;
    const int z    = blockIdx.z;
    const int kbase = z * kPerSplit;
    const int S    = kPerSplit / 64;
    const int warp = tid >> 5, lane = tid & 31;
    const int wm   = (warp >> 1) * (CTA_M / 2);
    const int wn   = (warp & 1) * 64;

    const uint32_t smbase = smem_u32(sm);
    const uint32_t a_lane = (uint32_t)((wm + (lane & 15)) * A_ROW_B + (lane >> 4) * 16);
    const uint32_t b_lane = (uint32_t)(CTA_M * A_ROW_B + (lane & 15) * B_ROW_B
                                       + (wn + (lane >> 4) * 8) * 2);

    auto prefetch = [&](int s) {
        uint32_t st = smbase + (uint32_t)((s % 3) * STG);
        const int k0 = kbase + s * 64;
        #pragma unroll
        for (int i = 0; i < CTA_M / 16; i++) {   // A: CTA_M x 64 (CTA_M*8 chunks / 128 thr)
            int c = tid + 128 * i;
            int row = c >> 3, col = (c & 7) * 8;
            CP_ASYNC16(st + (uint32_t)(row * A_ROW_B + col * 2),
                       A + (size_t)(m0 + row) * lda + k0 + col);
        }
        #pragma unroll
        for (int i = 0; i < 8; i++) {            // B: 64 x 128 (1024 chunks / 128 thr)
            int c = tid + 128 * i;
            int row = c >> 4, col = (c & 15) * 8;
            CP_ASYNC16(st + (uint32_t)(CTA_M * A_ROW_B + row * B_ROW_B + col * 2),
                       B + (size_t)(k0 + row) * ldb + n0 + col);
        }
        CP_COMMIT();
    };

    float acc[MT][8][4] = {};
    prefetch(0); prefetch(1);

    for (int s = 0; s < S; s++) {
        if (s + 1 < S) asm volatile("cp.async.wait_group 1;\n" ::: "memory");
        else           asm volatile("cp.async.wait_group 0;\n" ::: "memory");
        __syncthreads();
        if (s + 2 < S) prefetch(s + 2);

        const uint32_t st = smbase + (uint32_t)((s % 3) * STG);
        const uint32_t a0 = st + a_lane;
        const uint32_t b0a = st + b_lane;
        #pragma unroll
        for (int kk = 0; kk < 64; kk += 16) {
            uint32_t af[MT][4], bfr[4][4];
            #pragma unroll
            for (int mt = 0; mt < MT; mt++)
                ldmatrix_x4_a(af[mt], a0 + (uint32_t)(mt * 16 * A_ROW_B + kk * 2));
            #pragma unroll
            for (int g = 0; g < 4; g++)
                ldmatrix_x4_t(bfr[g], b0a + (uint32_t)(kk * B_ROW_B + g * 32));
            #pragma unroll
            for (int mt = 0; mt < MT; mt++)
                #pragma unroll
                for (int nt = 0; nt < 8; nt++)
                    mma_bf16(acc[mt][nt], af[mt],
                             bfr[nt >> 1][(nt & 1) * 2], bfr[nt >> 1][(nt & 1) * 2 + 1]);
        }
    }

    if (MODE == 0) {
        float* o = out + (size_t)z * (BATCH * ldc);
        #pragma unroll
        for (int mt = 0; mt < MT; mt++) {
            #pragma unroll
            for (int nt = 0; nt < 8; nt++) {
                int r = m0 + wm + mt * 16 + (lane >> 2);
                int c = n0 + wn + nt * 8 + (lane & 3) * 2;
                *reinterpret_cast<float2*>(&o[(size_t)r * ldc + c]) =
                    make_float2(acc[mt][nt][0], acc[mt][nt][1]);
                *reinterpret_cast<float2*>(&o[(size_t)(r + 8) * ldc + c]) =
                    make_float2(acc[mt][nt][2], acc[mt][nt][3]);
            }
        }
    } else {
        #pragma unroll
        for (int mt = 0; mt < MT; mt++) {
            #pragma unroll
            for (int nt = 0; nt < 8; nt++) {
                int c = n0 + wn + nt * 8 + (lane & 3) * 2;
                float b0 = bias[c], b1 = bias[c + 1];
                #pragma unroll
                for (int pr = 0; pr < 2; pr++) {
                    int r = m0 + wm + mt * 16 + (lane >> 2) + 8 * pr;
                    size_t o = (size_t)r * ldc + c;
                    float2 old = *reinterpret_cast<const float2*>(&out[o]);
                    float v0 = acc[mt][nt][2 * pr]     + old.x + b0;
                    float v1 = acc[mt][nt][2 * pr + 1] + old.y + b1;
                    *reinterpret_cast<float2*>(&out[o]) = make_float2(v0, v1);
                    float xv0 = x[o] - sigmoidf(v0);
                    float xv1 = x[o + 1] - sigmoidf(v1);
                    __nv_bfloat16 h0, l0, h1, l1;
                    split_bf16(xv0, h0, l0);
                    split_bf16(xv1, h1, l1);
                    size_t ab = (size_t)r * KP_ENC + c;
                    aeb[ab]             = h0; aeb[ab + 1]             = h1;
                    aeb[ab + K_ENC]     = h0; aeb[ab + K_ENC + 1]     = h1;
                    aeb[ab + 2 * K_ENC] = l0; aeb[ab + 2 * K_ENC + 1] = l1;
                }
            }
        }
    }
}

#define SMEM_M128 (3 * (128 * A_ROW_B + 64 * B_ROW_B))   // 107520
#define SMEM_M64  (3 * (64  * A_ROW_B + 64 * B_ROW_B))   // 79872

// ---------------- setup kernels (exactly 3 launches; harness adds 2 before) ----
__global__ void build_w1_kernel(const float* __restrict__ ek, const float* __restrict__ er) {
    int idx = blockIdx.x * blockDim.x + threadIdx.x;
    if (idx >= K_ENC * GATE) return;
    int row = idx / GATE;
    int n   = idx - row * GATE;
    float v;
    if (row < PIX) {
        int r = row >> 6, c = row & 63;
        v = 0.f;
        #pragma unroll
        for (int dr = 0; dr < 3; dr++) {
            int rr = r - dr;
            if (rr >= 0 && (rr & 1) == 0) {
                int pr = rr >> 1;
                #pragma unroll
                for (int dc = 0; dc < 3; dc++) {
                    int cc = c - dc;
                    if (cc >= 0 && (cc & 1) == 0) {
                        int pc = cc >> 1;
                        v += ek[(((pr * 32 + pc) * 9) + dr * 3 + dc) * GATE + n];
                    }
                }
            }
        }
    } else if (row < PIX + UNITS) {
        v = er[(row - PIX) * GATE + n];
    } else {
        int u = row - PIX - UNITS;
        v = ek[(9216 + u) * GATE + n] + ek[(9472 + u) * GATE + n];
    }
    __nv_bfloat16 hi, lo; split_bf16(v, hi, lo);
    g_Be[(size_t)row * GATE + n]               = hi;
    g_Be[(size_t)(K_ENC + row) * GATE + n]     = lo;
    g_Be[(size_t)(2 * K_ENC + row) * GATE + n] = hi;
}

__global__ void build_w2c_kernel(const float* __restrict__ dk, const float* __restrict__ dr,
                                 const float* __restrict__ wd) {
    int idx = blockIdx.x * blockDim.x + threadIdx.x;
    if (idx < K_DEC * GATE) {
        int row = idx / GATE;
        int n   = idx - row * GATE;
        float v = (row < UNITS) ? dk[row * GATE + n] : dr[(row - UNITS) * GATE + n];
        __nv_bfloat16 hi, lo; split_bf16(v, hi, lo);
        g_Bd[row * GATE + n]               = hi;
        g_Bd[(K_DEC + row) * GATE + n]     = lo;
        g_Bd[(2 * K_DEC + row) * GATE + n] = hi;
    }
    int j = idx - K_DEC * GATE;
    if (j >= 0 && j < K_CAN * PIX) {
        int row = j / PIX;
        int n   = j - row * PIX;
        float v = wd[j];
        __nv_bfloat16 hi, lo; split_bf16(v, hi, lo);
        g_Bc[row * PIX + n]               = hi;
        g_Bc[(K_CAN + row) * PIX + n]     = lo;
        g_Bc[(2 * K_CAN + row) * PIX + n] = hi;
    }
}

__global__ void init_xhat_kernel(const float* __restrict__ x, float* __restrict__ canvas) {
    int i = blockIdx.x * blockDim.x + threadIdx.x;
    canvas[i] = 0.f;
    {
        int b = i >> 12, p = i & (PIX - 1);
        float v = x[i] - 0.5f;
        __nv_bfloat16 hi, lo; split_bf16(v, hi, lo);
        size_t base = (size_t)b * KP_ENC + p;
        g_Aeb[base]             = hi;
        g_Aeb[base + K_ENC]     = hi;
        g_Aeb[base + 2 * K_ENC] = lo;
    }
    if (i < BATCH * UNITS) { g_ce[i] = 0.f; g_cd[i] = 0.f; }
    if (i < BATCH * 3 * 2 * UNITS) {
        int b = i / (3 * 2 * UNITS);
        int r = i - b * (3 * 2 * UNITS);
        int seg = r / (2 * UNITS), off = r - seg * (2 * UNITS);
        g_Aeb[(size_t)b * KP_ENC + seg * K_ENC + PIX + off] = __float2bfloat16(0.f);
    }
    if (i < BATCH * 3 * UNITS) {
        int b = i / (3 * UNITS);
        int r = i - b * (3 * UNITS);
        int seg = r / UNITS, off = r - seg * UNITS;
        g_Adb[(size_t)b * KP_DEC + seg * K_DEC + UNITS + off] = __float2bfloat16(0.f);
    }
}

// ---------------- fused enc LSTM (split reduce) + attention ----------------
__global__ void lstm_enc_attn_kernel(const float* __restrict__ part,
                                     const float* __restrict__ bias,
                                     const float* __restrict__ Wenc,
                                     const float* __restrict__ benc) {
    const int b = blockIdx.x;
    const int u = threadIdx.x;
    __shared__ float sh[UNITS];
    __shared__ float lg[10];
    __shared__ float attn[10];

    float gi = bias[u], gf = bias[UNITS + u], gg = bias[2 * UNITS + u], go = bias[3 * UNITS + u];
    const size_t roff = (size_t)b * GATE + u;
    #pragma unroll
    for (int s = 0; s < ENC_SPLITS; s++) {
        const float* p = part + (size_t)s * (BATCH * GATE) + roff;
        gi += p[0]; gf += p[UNITS]; gg += p[2 * UNITS]; go += p[3 * UNITS];
    }
    int idx = b * UNITS + u;
    float cn = sigmoidf(gf) * g_ce[idx] + sigmoidf(gi) * tanhf(gg);
    float hn = sigmoidf(go) * tanhf(cn);
    g_ce[idx] = cn;
    sh[u] = hn;
    {
        __nv_bfloat16 hi, lo; split_bf16(hn, hi, lo);
        size_t base = (size_t)b * KP_ENC + PIX + u;
        g_Aeb[base]             = hi;
        g_Aeb[base + K_ENC]     = hi;
        g_Aeb[base + 2 * K_ENC] = lo;
    }
    if (u < 10) lg[u] = benc[u];
    __syncthreads();

    float p10[10];
    float hv = sh[u];
    #pragma unroll
    for (int j = 0; j < 10; j++) p10[j] = hv * Wenc[u * 10 + j];
    #pragma unroll
    for (int j = 0; j < 10; j++)
        #pragma unroll
        for (int off = 16; off > 0; off >>= 1)
            p10[j] += __shfl_down_sync(0xffffffffu, p10[j], off);
    if ((u & 31) == 0)
        for (int j = 0; j < 10; j++) atomicAdd(&lg[j], p10[j]);
    __syncthreads();
    if (u == 0) {
        float m = lg[0];
        for (int j = 1; j < 10; j++) m = fmaxf(m, lg[j]);
        float ssum = 0.f, e[10];
        for (int j = 0; j < 10; j++) { e[j] = expf(lg[j] - m); ssum += e[j]; }
        float inv = 1.f / ssum;
        for (int j = 0; j < 10; j++) attn[j] = e[j] * inv;
    }
    __syncthreads();
    float zacc = 0.f;
    #pragma unroll
    for (int j = 0; j < 10; j++) zacc += attn[j] * Wenc[u * 10 + j];
    __nv_bfloat16 hi, lo; split_bf16(zacc, hi, lo);
    size_t bd = (size_t)b * KP_DEC + u;
    g_Adb[bd]             = hi;
    g_Adb[bd + K_DEC]     = hi;
    g_Adb[bd + 2 * K_DEC] = lo;
}

// ---------------- dec LSTM (split reduce) ----------------
__global__ void lstm_dec_kernel(const float* __restrict__ part, const float* __restrict__ bias) {
    int idx = blockIdx.x * blockDim.x + threadIdx.x;
    int b = idx / UNITS, u = idx - b * UNITS;
    float gi = bias[u], gf = bias[UNITS + u], gg = bias[2 * UNITS + u], go = bias[3 * UNITS + u];
    size_t roff = (size_t)b * GATE + u;
    #pragma unroll
    for (int s = 0; s < DEC_SPLITS; s++) {
        const float* p = part + (size_t)s * (BATCH * GATE) + roff;
        gi += p[0]; gf += p[UNITS]; gg += p[2 * UNITS]; go += p[3 * UNITS];
    }
    float cn = sigmoidf(gf) * g_cd[idx] + sigmoidf(gi) * tanhf(gg);
    float hn = sigmoidf(go) * tanhf(cn);
    g_cd[idx] = cn;
    __nv_bfloat16 hi, lo; split_bf16(hn, hi, lo);
    size_t be = (size_t)b * KP_ENC + PIX + UNITS + u;
    g_Aeb[be]             = hi;
    g_Aeb[be + K_ENC]     = hi;
    g_Aeb[be + 2 * K_ENC] = lo;
    size_t bd = (size_t)b * KP_DEC + UNITS + u;
    g_Adb[bd]             = hi;
    g_Adb[bd + K_DEC]     = hi;
    g_Adb[bd + 2 * K_DEC] = lo;
    size_t bc = (size_t)b * KP_CAN + u;
    g_Acb[bc]             = hi;
    g_Acb[bc + K_CAN]     = hi;
    g_Acb[bc + 2 * K_CAN] = lo;
}

// ---------------- launcher ----------------
extern "C" void kernel_launch(void* const* d_in, const int* in_sizes, int n_in,
                              void* d_out, int out_size) {
    const float* x          = (const float*)d_in[0];
    const float* enc_kernel = (const float*)d_in[1];
    const float* enc_rec    = (const float*)d_in[2];
    const float* enc_bias   = (const float*)d_in[3];
    const float* dec_kernel = (const float*)d_in[4];
    const float* dec_rec    = (const float*)d_in[5];
    const float* dec_bias   = (const float*)d_in[6];
    const float* W_enc      = (const float*)d_in[7];
    const float* b_enc      = (const float*)d_in[8];
    const float* W_dec      = (const float*)d_in[9];
    const float* b_dec      = (const float*)d_in[10];
    float* canvas = (float*)d_out;

    __nv_bfloat16 *Ae, *Ad, *Ac, *Be, *Bd, *Bc;
    float *part;
    cudaGetSymbolAddress((void**)&Ae,  g_Aeb);
    cudaGetSymbolAddress((void**)&Ad,  g_Adb);
    cudaGetSymbolAddress((void**)&Ac,  g_Acb);
    cudaGetSymbolAddress((void**)&Be,  g_Be);
    cudaGetSymbolAddress((void**)&Bd,  g_Bd);
    cudaGetSymbolAddress((void**)&Bc,  g_Bc);
    cudaGetSymbolAddress((void**)&part, g_part);

    cudaFuncSetAttribute(gemm_hmma<128, 0>, cudaFuncAttributeMaxDynamicSharedMemorySize, SMEM_M128);
    cudaFuncSetAttribute(gemm_hmma<64, 1>,  cudaFuncAttributeMaxDynamicSharedMemorySize, SMEM_M64);

    // ---- setup: exactly 3 launches (enc GEMM stays in the ncu -s 5 slot) ----
    build_w1_kernel<<<(K_ENC * GATE + 255) / 256, 256>>>(enc_kernel, enc_rec);
    build_w2c_kernel<<<(K_DEC * GATE + K_CAN * PIX + 255) / 256, 256>>>(dec_kernel, dec_rec, W_dec);
    init_xhat_kernel<<<(BATCH * PIX) / 256, 256>>>(x, canvas);

    // ---- 10 sequential DRAW steps ----
    for (int t = 0; t < STEPS; t++) {
        gemm_hmma<128, 0><<<dim3(GATE / 128, BATCH / 128, ENC_SPLITS), 128, SMEM_M128>>>(
            Ae, KP_ENC, Be, GATE, part, GATE, KP_ENC / ENC_SPLITS, nullptr, nullptr, nullptr);

        lstm_enc_attn_kernel<<<BATCH, 256>>>(part, enc_bias, W_enc, b_enc);

        gemm_hmma<128, 0><<<dim3(GATE / 128, BATCH / 128, DEC_SPLITS), 128, SMEM_M128>>>(
            Ad, KP_DEC, Bd, GATE, part, GATE, KP_DEC / DEC_SPLITS, nullptr, nullptr, nullptr);

        lstm_dec_kernel<<<(BATCH * UNITS) / 256, 256>>>(part, dec_bias);

        gemm_hmma<64, 1><<<dim3(PIX / 128, BATCH / 64, 1), 128, SMEM_M64>>>(
            Ac, KP_CAN, Bc, PIX, canvas, PIX, KP_CAN, b_dec, x, Ae);
    }
}

// round 16
// speedup vs baseline: 1.2106x; 1.0968x over previous
#include <cuda_runtime.h>
#include <cuda_bf16.h>
#include <math.h>
#include <stdint.h>

// ---------------- problem constants ----------------
#define IMGD   64
#define BATCH  512
#define UNITS  256
#define STEPS  10
#define GATE   (4*UNITS)          // 1024
#define PIX    (IMGD*IMGD)        // 4096
#define K_ENC  (PIX + 2*UNITS)    // 4608
#define K_DEC  (2*UNITS)          // 512
#define K_CAN  UNITS              // 256
#define KP_ENC (3*K_ENC)          // 13824
#define KP_DEC (3*K_DEC)          // 1536
#define KP_CAN (3*K_CAN)          // 768

#define ENC_SPLITS 9              // grid (8,4,9) = 288 CTAs @ 2/SM ~ 1 wave
#define DEC_SPLITS 8              // grid (8,4,8) = 256 CTAs

// ---------------- scratch (device globals) ----------------
__device__ __align__(16) __nv_bfloat16 g_Be[(size_t)KP_ENC * GATE];
__device__ __align__(16) __nv_bfloat16 g_Bd[(size_t)KP_DEC * GATE];
__device__ __align__(16) __nv_bfloat16 g_Bc[(size_t)KP_CAN * PIX];
__device__ __align__(16) __nv_bfloat16 g_Aeb[(size_t)BATCH * KP_ENC];
__device__ __align__(16) __nv_bfloat16 g_Adb[(size_t)BATCH * KP_DEC];
__device__ __align__(16) __nv_bfloat16 g_Acb[(size_t)BATCH * KP_CAN];
__device__ __align__(16) float g_part[(size_t)ENC_SPLITS * BATCH * GATE];
__device__ __align__(16) float g_ce[BATCH * UNITS];
__device__ __align__(16) float g_cd[BATCH * UNITS];

__device__ __forceinline__ float sigmoidf(float x) { return 1.f / (1.f + expf(-x)); }
__device__ __forceinline__ void split_bf16(float v, __nv_bfloat16& hi, __nv_bfloat16& lo) {
    hi = __float2bfloat16(v);
    lo = __float2bfloat16(v - __bfloat162float(hi));
}

// ---------------- PTX helpers ----------------
__device__ __forceinline__ uint32_t smem_u32(const void* p) {
    uint32_t a;
    asm("{ .reg .u64 t; cvta.to.shared.u64 t, %1; cvt.u32.u64 %0, t; }" : "=r"(a) : "l"(p));
    return a;
}
#define CP_ASYNC16(dst, src) \
    asm volatile("cp.async.cg.shared.global [%0], [%1], 16;\n" :: "r"(dst), "l"(src))
#define CP_COMMIT() asm volatile("cp.async.commit_group;\n")

__device__ __forceinline__ void ldmatrix_x4_a(uint32_t* r, uint32_t a) {
    asm volatile("ldmatrix.sync.aligned.m8n8.x4.shared.b16 {%0,%1,%2,%3}, [%4];\n"
                 : "=r"(r[0]), "=r"(r[1]), "=r"(r[2]), "=r"(r[3]) : "r"(a));
}
__device__ __forceinline__ void ldmatrix_x4_t(uint32_t* r, uint32_t a) {
    asm volatile("ldmatrix.sync.aligned.m8n8.x4.trans.shared.b16 {%0,%1,%2,%3}, [%4];\n"
                 : "=r"(r[0]), "=r"(r[1]), "=r"(r[2]), "=r"(r[3]) : "r"(a));
}
__device__ __forceinline__ void mma_bf16(float* d, const uint32_t* a, uint32_t b0, uint32_t b1) {
    asm volatile("mma.sync.aligned.m16n8k16.row.col.f32.bf16.bf16.f32 "
                 "{%0,%1,%2,%3}, {%4,%5,%6,%7}, {%8,%9}, {%0,%1,%2,%3};\n"
                 : "+f"(d[0]), "+f"(d[1]), "+f"(d[2]), "+f"(d[3])
                 : "r"(a[0]), "r"(a[1]), "r"(a[2]), "r"(a[3]), "r"(b0), "r"(b1));
}

// ---------------- HMMA GEMM: CTA_M x 128 tile, 4 warps (2x2), BK=32, 4 stages, 2 CTA/SM ----
// Round-13-validated loop body. CTA_M=128 for enc/dec (64x64 warp tile, tensor 62%),
// CTA_M=64 for canvas (256-CTA grid, distributed fused epilogue).
#define A_ROW_B 80                 // 32*2 + 16 pad
#define B_ROW_B 272                // 128*2 + 16 pad

template<int CTA_M, int MODE>
__global__ void __launch_bounds__(128, 2) gemm_hmma(
    const __nv_bfloat16* __restrict__ A, int lda,
    const __nv_bfloat16* __restrict__ B, int ldb,
    float* __restrict__ out, int ldc, int kPerSplit,
    const float* __restrict__ bias,
    const float* __restrict__ x, __nv_bfloat16* __restrict__ aeb)
{
    constexpr int MT  = CTA_M / 32;                       // acc m-tiles per warp
    constexpr int STG = CTA_M * A_ROW_B + 32 * B_ROW_B;   // stage bytes

    extern __shared__ __align__(16) char sm[];
    const int tid  = threadIdx.x;
    const int m0   = blockIdx.y * CTA_M;
    const int n0   = blockIdx.x * 128;
    const int z    = blockIdx.z;
    const int kbase = z * kPerSplit;
    const int S    = kPerSplit / 32;
    const int warp = tid >> 5, lane = tid & 31;
    const int wm   = (warp >> 1) * (CTA_M / 2);
    const int wn   = (warp & 1) * 64;

    const uint32_t smbase = smem_u32(sm);
    const uint32_t a_lane = (uint32_t)((wm + (lane & 15)) * A_ROW_B + (lane >> 4) * 16);
    const uint32_t b_lane = (uint32_t)(CTA_M * A_ROW_B + (lane & 15) * B_ROW_B
                                       + (wn + (lane >> 4) * 8) * 2);

    auto prefetch = [&](int s) {
        uint32_t st = smbase + (uint32_t)((s & 3) * STG);
        const int k0 = kbase + s * 32;
        #pragma unroll
        for (int i = 0; i < CTA_M / 32; i++) {   // A: CTA_M x 32 (CTA_M*4 chunks / 128 thr)
            int c = tid + 128 * i;
            int row = c >> 2, col = (c & 3) * 8;
            CP_ASYNC16(st + (uint32_t)(row * A_ROW_B + col * 2),
                       A + (size_t)(m0 + row) * lda + k0 + col);
        }
        #pragma unroll
        for (int i = 0; i < 4; i++) {            // B: 32 x 128 (512 chunks / 128 thr)
            int c = tid + 128 * i;
            int row = c >> 4, col = (c & 15) * 8;
            CP_ASYNC16(st + (uint32_t)(CTA_M * A_ROW_B + row * B_ROW_B + col * 2),
                       B + (size_t)(k0 + row) * ldb + n0 + col);
        }
        CP_COMMIT();
    };

    float acc[MT][8][4] = {};
    prefetch(0); prefetch(1); prefetch(2);

    for (int s = 0; s < S; s++) {
        int rem = S - 1 - s;
        if (rem >= 2)      asm volatile("cp.async.wait_group 2;\n" ::: "memory");
        else if (rem == 1) asm volatile("cp.async.wait_group 1;\n" ::: "memory");
        else               asm volatile("cp.async.wait_group 0;\n" ::: "memory");
        __syncthreads();
        if (s + 3 < S) prefetch(s + 3);

        const uint32_t st = smbase + (uint32_t)((s & 3) * STG);
        const uint32_t a0 = st + a_lane;
        const uint32_t b0a = st + b_lane;
        #pragma unroll
        for (int kk = 0; kk < 32; kk += 16) {
            uint32_t af[MT][4], bfr[4][4];
            #pragma unroll
            for (int mt = 0; mt < MT; mt++)
                ldmatrix_x4_a(af[mt], a0 + (uint32_t)(mt * 16 * A_ROW_B + kk * 2));
            #pragma unroll
            for (int g = 0; g < 4; g++)
                ldmatrix_x4_t(bfr[g], b0a + (uint32_t)(kk * B_ROW_B + g * 32));
            #pragma unroll
            for (int mt = 0; mt < MT; mt++)
                #pragma unroll
                for (int nt = 0; nt < 8; nt++)
                    mma_bf16(acc[mt][nt], af[mt],
                             bfr[nt >> 1][(nt & 1) * 2], bfr[nt >> 1][(nt & 1) * 2 + 1]);
        }
    }

    if (MODE == 0) {
        float* o = out + (size_t)z * (BATCH * ldc);
        #pragma unroll
        for (int mt = 0; mt < MT; mt++) {
            #pragma unroll
            for (int nt = 0; nt < 8; nt++) {
                int r = m0 + wm + mt * 16 + (lane >> 2);
                int c = n0 + wn + nt * 8 + (lane & 3) * 2;
                *reinterpret_cast<float2*>(&o[(size_t)r * ldc + c]) =
                    make_float2(acc[mt][nt][0], acc[mt][nt][1]);
                *reinterpret_cast<float2*>(&o[(size_t)(r + 8) * ldc + c]) =
                    make_float2(acc[mt][nt][2], acc[mt][nt][3]);
            }
        }
    } else {
        #pragma unroll
        for (int mt = 0; mt < MT; mt++) {
            #pragma unroll
            for (int nt = 0; nt < 8; nt++) {
                int c = n0 + wn + nt * 8 + (lane & 3) * 2;
                float b0 = bias[c], b1 = bias[c + 1];
                #pragma unroll
                for (int pr = 0; pr < 2; pr++) {
                    int r = m0 + wm + mt * 16 + (lane >> 2) + 8 * pr;
                    size_t o = (size_t)r * ldc + c;
                    float2 old = *reinterpret_cast<const float2*>(&out[o]);
                    float v0 = acc[mt][nt][2 * pr]     + old.x + b0;
                    float v1 = acc[mt][nt][2 * pr + 1] + old.y + b1;
                    *reinterpret_cast<float2*>(&out[o]) = make_float2(v0, v1);
                    float xv0 = x[o] - sigmoidf(v0);
                    float xv1 = x[o + 1] - sigmoidf(v1);
                    __nv_bfloat16 h0, l0, h1, l1;
                    split_bf16(xv0, h0, l0);
                    split_bf16(xv1, h1, l1);
                    size_t ab = (size_t)r * KP_ENC + c;
                    aeb[ab]             = h0; aeb[ab + 1]             = h1;
                    aeb[ab + K_ENC]     = h0; aeb[ab + K_ENC + 1]     = h1;
                    aeb[ab + 2 * K_ENC] = l0; aeb[ab + 2 * K_ENC + 1] = l1;
                }
            }
        }
    }
}

#define SMEM_M128 (4 * (128 * A_ROW_B + 32 * B_ROW_B))   // 75776
#define SMEM_M64  (4 * (64  * A_ROW_B + 32 * B_ROW_B))   // 55296

// ---------------- setup kernels (exactly 3 launches; harness adds 2 before) ----
__global__ void build_w1_kernel(const float* __restrict__ ek, const float* __restrict__ er) {
    int idx = blockIdx.x * blockDim.x + threadIdx.x;
    if (idx >= K_ENC * GATE) return;
    int row = idx / GATE;
    int n   = idx - row * GATE;
    float v;
    if (row < PIX) {
        int r = row >> 6, c = row & 63;
        v = 0.f;
        #pragma unroll
        for (int dr = 0; dr < 3; dr++) {
            int rr = r - dr;
            if (rr >= 0 && (rr & 1) == 0) {
                int pr = rr >> 1;
                #pragma unroll
                for (int dc = 0; dc < 3; dc++) {
                    int cc = c - dc;
                    if (cc >= 0 && (cc & 1) == 0) {
                        int pc = cc >> 1;
                        v += ek[(((pr * 32 + pc) * 9) + dr * 3 + dc) * GATE + n];
                    }
                }
            }
        }
    } else if (row < PIX + UNITS) {
        v = er[(row - PIX) * GATE + n];
    } else {
        int u = row - PIX - UNITS;
        v = ek[(9216 + u) * GATE + n] + ek[(9472 + u) * GATE + n];
    }
    __nv_bfloat16 hi, lo; split_bf16(v, hi, lo);
    g_Be[(size_t)row * GATE + n]               = hi;
    g_Be[(size_t)(K_ENC + row) * GATE + n]     = lo;
    g_Be[(size_t)(2 * K_ENC + row) * GATE + n] = hi;
}

__global__ void build_w2c_kernel(const float* __restrict__ dk, const float* __restrict__ dr,
                                 const float* __restrict__ wd) {
    int idx = blockIdx.x * blockDim.x + threadIdx.x;
    if (idx < K_DEC * GATE) {
        int row = idx / GATE;
        int n   = idx - row * GATE;
        float v = (row < UNITS) ? dk[row * GATE + n] : dr[(row - UNITS) * GATE + n];
        __nv_bfloat16 hi, lo; split_bf16(v, hi, lo);
        g_Bd[row * GATE + n]               = hi;
        g_Bd[(K_DEC + row) * GATE + n]     = lo;
        g_Bd[(2 * K_DEC + row) * GATE + n] = hi;
    }
    int j = idx - K_DEC * GATE;
    if (j >= 0 && j < K_CAN * PIX) {
        int row = j / PIX;
        int n   = j - row * PIX;
        float v = wd[j];
        __nv_bfloat16 hi, lo; split_bf16(v, hi, lo);
        g_Bc[row * PIX + n]               = hi;
        g_Bc[(K_CAN + row) * PIX + n]     = lo;
        g_Bc[(2 * K_CAN + row) * PIX + n] = hi;
    }
}

__global__ void init_xhat_kernel(const float* __restrict__ x, float* __restrict__ canvas) {
    int i = blockIdx.x * blockDim.x + threadIdx.x;
    canvas[i] = 0.f;
    {
        int b = i >> 12, p = i & (PIX - 1);
        float v = x[i] - 0.5f;
        __nv_bfloat16 hi, lo; split_bf16(v, hi, lo);
        size_t base = (size_t)b * KP_ENC + p;
        g_Aeb[base]             = hi;
        g_Aeb[base + K_ENC]     = hi;
        g_Aeb[base + 2 * K_ENC] = lo;
    }
    if (i < BATCH * UNITS) { g_ce[i] = 0.f; g_cd[i] = 0.f; }
    if (i < BATCH * 3 * 2 * UNITS) {
        int b = i / (3 * 2 * UNITS);
        int r = i - b * (3 * 2 * UNITS);
        int seg = r / (2 * UNITS), off = r - seg * (2 * UNITS);
        g_Aeb[(size_t)b * KP_ENC + seg * K_ENC + PIX + off] = __float2bfloat16(0.f);
    }
    if (i < BATCH * 3 * UNITS) {
        int b = i / (3 * UNITS);
        int r = i - b * (3 * UNITS);
        int seg = r / UNITS, off = r - seg * UNITS;
        g_Adb[(size_t)b * KP_DEC + seg * K_DEC + UNITS + off] = __float2bfloat16(0.f);
    }
}

// ---------------- fused enc LSTM (split reduce) + attention ----------------
__global__ void lstm_enc_attn_kernel(const float* __restrict__ part,
                                     const float* __restrict__ bias,
                                     const float* __restrict__ Wenc,
                                     const float* __restrict__ benc) {
    const int b = blockIdx.x;
    const int u = threadIdx.x;
    __shared__ float sh[UNITS];
    __shared__ float lg[10];
    __shared__ float attn[10];

    float gi = bias[u], gf = bias[UNITS + u], gg = bias[2 * UNITS + u], go = bias[3 * UNITS + u];
    const size_t roff = (size_t)b * GATE + u;
    #pragma unroll
    for (int s = 0; s < ENC_SPLITS; s++) {
        const float* p = part + (size_t)s * (BATCH * GATE) + roff;
        gi += p[0]; gf += p[UNITS]; gg += p[2 * UNITS]; go += p[3 * UNITS];
    }
    int idx = b * UNITS + u;
    float cn = sigmoidf(gf) * g_ce[idx] + sigmoidf(gi) * tanhf(gg);
    float hn = sigmoidf(go) * tanhf(cn);
    g_ce[idx] = cn;
    sh[u] = hn;
    {
        __nv_bfloat16 hi, lo; split_bf16(hn, hi, lo);
        size_t base = (size_t)b * KP_ENC + PIX + u;
        g_Aeb[base]             = hi;
        g_Aeb[base + K_ENC]     = hi;
        g_Aeb[base + 2 * K_ENC] = lo;
    }
    if (u < 10) lg[u] = benc[u];
    __syncthreads();

    float p10[10];
    float hv = sh[u];
    #pragma unroll
    for (int j = 0; j < 10; j++) p10[j] = hv * Wenc[u * 10 + j];
    #pragma unroll
    for (int j = 0; j < 10; j++)
        #pragma unroll
        for (int off = 16; off > 0; off >>= 1)
            p10[j] += __shfl_down_sync(0xffffffffu, p10[j], off);
    if ((u & 31) == 0)
        for (int j = 0; j < 10; j++) atomicAdd(&lg[j], p10[j]);
    __syncthreads();
    if (u == 0) {
        float m = lg[0];
        for (int j = 1; j < 10; j++) m = fmaxf(m, lg[j]);
        float ssum = 0.f, e[10];
        for (int j = 0; j < 10; j++) { e[j] = expf(lg[j] - m); ssum += e[j]; }
        float inv = 1.f / ssum;
        for (int j = 0; j < 10; j++) attn[j] = e[j] * inv;
    }
    __syncthreads();
    float zacc = 0.f;
    #pragma unroll
    for (int j = 0; j < 10; j++) zacc += attn[j] * Wenc[u * 10 + j];
    __nv_bfloat16 hi, lo; split_bf16(zacc, hi, lo);
    size_t bd = (size_t)b * KP_DEC + u;
    g_Adb[bd]             = hi;
    g_Adb[bd + K_DEC]     = hi;
    g_Adb[bd + 2 * K_DEC] = lo;
}

// ---------------- dec LSTM (split reduce) ----------------
__global__ void lstm_dec_kernel(const float* __restrict__ part, const float* __restrict__ bias) {
    int idx = blockIdx.x * blockDim.x + threadIdx.x;
    int b = idx / UNITS, u = idx - b * UNITS;
    float gi = bias[u], gf = bias[UNITS + u], gg = bias[2 * UNITS + u], go = bias[3 * UNITS + u];
    size_t roff = (size_t)b * GATE + u;
    #pragma unroll
    for (int s = 0; s < DEC_SPLITS; s++) {
        const float* p = part + (size_t)s * (BATCH * GATE) + roff;
        gi += p[0]; gf += p[UNITS]; gg += p[2 * UNITS]; go += p[3 * UNITS];
    }
    float cn = sigmoidf(gf) * g_cd[idx] + sigmoidf(gi) * tanhf(gg);
    float hn = sigmoidf(go) * tanhf(cn);
    g_cd[idx] = cn;
    __nv_bfloat16 hi, lo; split_bf16(hn, hi, lo);
    size_t be = (size_t)b * KP_ENC + PIX + UNITS + u;
    g_Aeb[be]             = hi;
    g_Aeb[be + K_ENC]     = hi;
    g_Aeb[be + 2 * K_ENC] = lo;
    size_t bd = (size_t)b * KP_DEC + UNITS + u;
    g_Adb[bd]             = hi;
    g_Adb[bd + K_DEC]     = hi;
    g_Adb[bd + 2 * K_DEC] = lo;
    size_t bc = (size_t)b * KP_CAN + u;
    g_Acb[bc]             = hi;
    g_Acb[bc + K_CAN]     = hi;
    g_Acb[bc + 2 * K_CAN] = lo;
}

// ---------------- launcher ----------------
extern "C" void kernel_launch(void* const* d_in, const int* in_sizes, int n_in,
                              void* d_out, int out_size) {
    const float* x          = (const float*)d_in[0];
    const float* enc_kernel = (const float*)d_in[1];
    const float* enc_rec    = (const float*)d_in[2];
    const float* enc_bias   = (const float*)d_in[3];
    const float* dec_kernel = (const float*)d_in[4];
    const float* dec_rec    = (const float*)d_in[5];
    const float* dec_bias   = (const float*)d_in[6];
    const float* W_enc      = (const float*)d_in[7];
    const float* b_enc      = (const float*)d_in[8];
    const float* W_dec      = (const float*)d_in[9];
    const float* b_dec      = (const float*)d_in[10];
    float* canvas = (float*)d_out;

    __nv_bfloat16 *Ae, *Ad, *Ac, *Be, *Bd, *Bc;
    float *part;
    cudaGetSymbolAddress((void**)&Ae,  g_Aeb);
    cudaGetSymbolAddress((void**)&Ad,  g_Adb);
    cudaGetSymbolAddress((void**)&Ac,  g_Acb);
    cudaGetSymbolAddress((void**)&Be,  g_Be);
    cudaGetSymbolAddress((void**)&Bd,  g_Bd);
    cudaGetSymbolAddress((void**)&Bc,  g_Bc);
    cudaGetSymbolAddress((void**)&part, g_part);

    cudaFuncSetAttribute(gemm_hmma<128, 0>, cudaFuncAttributeMaxDynamicSharedMemorySize, SMEM_M128);
    cudaFuncSetAttribute(gemm_hmma<64, 1>,  cudaFuncAttributeMaxDynamicSharedMemorySize, SMEM_M64);

    // ---- setup: exactly 3 launches (enc GEMM stays in the ncu -s 5 slot) ----
    build_w1_kernel<<<(K_ENC * GATE + 255) / 256, 256>>>(enc_kernel, enc_rec);
    build_w2c_kernel<<<(K_DEC * GATE + K_CAN * PIX + 255) / 256, 256>>>(dec_kernel, dec_rec, W_dec);
    init_xhat_kernel<<<(BATCH * PIX) / 256, 256>>>(x, canvas);

    // ---- 10 sequential DRAW steps ----
    for (int t = 0; t < STEPS; t++) {
        gemm_hmma<128, 0><<<dim3(GATE / 128, BATCH / 128, ENC_SPLITS), 128, SMEM_M128>>>(
            Ae, KP_ENC, Be, GATE, part, GATE, KP_ENC / ENC_SPLITS, nullptr, nullptr, nullptr);

        lstm_enc_attn_kernel<<<BATCH, 256>>>(part, enc_bias, W_enc, b_enc);

        gemm_hmma<128, 0><<<dim3(GATE / 128, BATCH / 128, DEC_SPLITS), 128, SMEM_M128>>>(
            Ad, KP_DEC, Bd, GATE, part, GATE, KP_DEC / DEC_SPLITS, nullptr, nullptr, nullptr);

        lstm_dec_kernel<<<(BATCH * UNITS) / 256, 256>>>(part, dec_bias);

        gemm_hmma<64, 1><<<dim3(PIX / 128, BATCH / 64, 1), 128, SMEM_M64>>>(
            Ac, KP_CAN, Bc, PIX, canvas, PIX, KP_CAN, b_dec, x, Ae);
    }
}